// round 1
// baseline (speedup 1.0000x reference)
#include <cuda_runtime.h>
#include <math.h>

#define T_SNAP 4
#define EQ     4096
#define NNODES 8192
#define H      32
#define W_WORDS 128              // EQ/32 bit-words per node mask
#define CAP    512               // per-(t,q) included-edge list capacity

#define MASK_WORDS (T_SNAP * 2 * NNODES * W_WORDS)  // 8,388,608 words = 32MB

// Scratch (static device globals — no runtime allocation)
__device__ __align__(16) unsigned g_RA[MASK_WORDS];
__device__ __align__(16) unsigned g_RB[MASK_WORDS];
__device__ int   g_cnt[T_SNAP * EQ];
__device__ int   g_list[T_SNAP * EQ * CAP];
__device__ float g_tops[T_SNAP * EQ * 3];

__device__ __forceinline__ int moff(int t, int m, int n, int w) {
    return ((t * 2 + m) * NNODES + n) * W_WORDS + w;
}

// ---------------------------------------------------------------------------
// 1) clear seed-mask buffer A and the per-query counters
__global__ void k_clear() {
    int i = blockIdx.x * blockDim.x + threadIdx.x;
    if (i < MASK_WORDS / 4) {
        ((uint4*)g_RA)[i] = make_uint4(0u, 0u, 0u, 0u);
    }
    if (i < T_SNAP * EQ) g_cnt[i] = 0;
}

// 2) seed: bit q set at node uq[q] (mask 0) / vq[q] (mask 1), same seeds all t
__global__ void k_seed(const int* __restrict__ ei) {
    int q = blockIdx.x * blockDim.x + threadIdx.x;
    if (q >= EQ) return;
    int u = ei[(T_SNAP - 1) * 2 * EQ + q];
    int v = ei[(T_SNAP - 1) * 2 * EQ + EQ + q];
    unsigned bit = 1u << (q & 31);
    int w = q >> 5;
#pragma unroll
    for (int t = 0; t < T_SNAP; t++) {
        atomicOr(&g_RA[moff(t, 0, u, w)], bit);
        atomicOr(&g_RA[moff(t, 1, v, w)], bit);
    }
}

// 3) copy between ping-pong buffers (dir 0: A->B, dir 1: B->A)
__global__ void k_copy(int dir) {
    int i = blockIdx.x * blockDim.x + threadIdx.x;
    if (i >= MASK_WORDS / 4) return;
    if (dir == 0) ((uint4*)g_RB)[i] = ((const uint4*)g_RA)[i];
    else          ((uint4*)g_RA)[i] = ((const uint4*)g_RB)[i];
}

// 4) one backward hop, simultaneous semantics: B[src] |= A[dst]  (B init = A)
__global__ void k_hop(const int* __restrict__ ei) {
    int idx = blockIdx.x * blockDim.x + threadIdx.x;
    if (idx >= T_SNAP * EQ * W_WORDS) return;
    int w = idx & (W_WORDS - 1);
    int e = (idx >> 7) & (EQ - 1);
    int t = idx >> 19;
    int src = __ldg(&ei[t * 2 * EQ + e]);
    int dst = __ldg(&ei[t * 2 * EQ + EQ + e]);
    unsigned a0 = g_RA[moff(t, 0, dst, w)];
    if (a0) atomicOr(&g_RB[moff(t, 0, src, w)], a0);
    unsigned a1 = g_RA[moff(t, 1, dst, w)];
    if (a1) atomicOr(&g_RB[moff(t, 1, src, w)], a1);
}

// 5) inclusion: edge e in query q's merged subgraph iff both endpoints reached
//    (from u) or both reached (from v). Append dst to q's list (dedup is
//    implicit: each (t,e,q) bit fires once).
__global__ void k_incl(const int* __restrict__ ei) {
    int idx = blockIdx.x * blockDim.x + threadIdx.x;
    if (idx >= T_SNAP * EQ * W_WORDS) return;
    int w = idx & (W_WORDS - 1);
    int e = (idx >> 7) & (EQ - 1);
    int t = idx >> 19;
    int src = __ldg(&ei[t * 2 * EQ + e]);
    int dst = __ldg(&ei[t * 2 * EQ + EQ + e]);
    unsigned mu = g_RB[moff(t, 0, src, w)] & g_RB[moff(t, 0, dst, w)];
    unsigned mv = g_RB[moff(t, 1, src, w)] & g_RB[moff(t, 1, dst, w)];
    unsigned m = mu | mv;
    while (m) {
        int b = __ffs(m) - 1;
        m &= m - 1;
        int q = (w << 5) + b;
        int pos = atomicAdd(&g_cnt[t * EQ + q], 1);
        if (pos < CAP) g_list[(t * EQ + q) * CAP + pos] = dst;
    }
}

// 6) top-3 in-degree values per (t, q): count duplicate dst's in the tiny list
__global__ void k_top3() {
    int idx = blockIdx.x * blockDim.x + threadIdx.x;
    if (idx >= T_SNAP * EQ) return;
    int k = g_cnt[idx];
    if (k > CAP) k = CAP;
    const int* lst = &g_list[idx * CAP];
    float t0 = 0.f, t1 = 0.f, t2 = 0.f;
    for (int i = 0; i < k; i++) {
        int d = lst[i];
        bool dup = false;
        for (int j = 0; j < i; j++)
            if (lst[j] == d) { dup = true; break; }
        if (dup) continue;
        int c = 1;
        for (int j = i + 1; j < k; j++)
            if (lst[j] == d) c++;
        float f = (float)c;
        if (f > t0)      { t2 = t1; t1 = t0; t0 = f; }
        else if (f > t1) { t2 = t1; t1 = f; }
        else if (f > t2) { t2 = f; }
    }
    g_tops[idx * 3 + 0] = t0;
    g_tops[idx * 3 + 1] = t1;
    g_tops[idx * 3 + 2] = t2;
}

// 7) fused GCN(1->H) + GRU over T snapshots, one thread per pooled node
__global__ void __launch_bounds__(128)
k_gru(const float* __restrict__ Wg,  const float* __restrict__ bg,
      const float* __restrict__ Wih, const float* __restrict__ Whh,
      const float* __restrict__ bih, const float* __restrict__ bhh,
      float* __restrict__ out) {
    __shared__ float sWih[3 * H * H];
    __shared__ float sWhh[3 * H * H];
    __shared__ float sbih[3 * H];
    __shared__ float sbhh[3 * H];
    __shared__ float sWg[H];
    __shared__ float sbg[H];

    int tid = threadIdx.x;
    for (int i = tid; i < 3 * H * H; i += 128) {
        sWih[i] = Wih[i];
        sWhh[i] = Whh[i];
    }
    for (int i = tid; i < 3 * H; i += 128) {
        sbih[i] = bih[i];
        sbhh[i] = bhh[i];
    }
    if (tid < H) { sWg[tid] = Wg[tid]; sbg[tid] = bg[tid]; }
    __syncthreads();

    int b = blockIdx.x * 128 + tid;
    if (b >= EQ * 3) return;
    int q = b / 3;
    int p = b - q * 3;

    float h[H];
#pragma unroll
    for (int j = 0; j < H; j++) h[j] = 0.f;

    for (int t = 0; t < T_SNAP; t++) {
        float v = g_tops[(t * EQ + q) * 3 + p];
        float x[H];
#pragma unroll
        for (int kk = 0; kk < H; kk++) {
            float xv = v * sWg[kk] + sbg[kk];
            x[kk] = xv > 0.f ? xv : 0.f;
        }
        // stage z and n through small (local) arrays so h[] stays in registers
        float zA[H], nA[H];
        for (int j = 0; j < H; j++) {
            float gir = sbih[j], giz = sbih[j + H], gig = sbih[j + 2 * H];
            float ghr = sbhh[j], ghz = sbhh[j + H], ghg = sbhh[j + 2 * H];
#pragma unroll
            for (int kk = 0; kk < H; kk++) {
                gir += sWih[j * H + kk] * x[kk];
                giz += sWih[(j + H) * H + kk] * x[kk];
                gig += sWih[(j + 2 * H) * H + kk] * x[kk];
                ghr += sWhh[j * H + kk] * h[kk];
                ghz += sWhh[(j + H) * H + kk] * h[kk];
                ghg += sWhh[(j + 2 * H) * H + kk] * h[kk];
            }
            float r = 1.f / (1.f + expf(-(gir + ghr)));
            float z = 1.f / (1.f + expf(-(giz + ghz)));
            float n = tanhf(gig + r * ghg);
            zA[j] = z;
            nA[j] = n;
        }
#pragma unroll
        for (int j = 0; j < H; j++)
            h[j] = (1.f - zA[j]) * nA[j] + zA[j] * h[j];
    }

#pragma unroll
    for (int j = 0; j < H; j++) out[b * H + j] = h[j];
}

// ---------------------------------------------------------------------------
extern "C" void kernel_launch(void* const* d_in, const int* in_sizes, int n_in,
                              void* d_out, int out_size) {
    const int*   ei  = (const int*)d_in[0];
    const float* Wg  = (const float*)d_in[1];
    const float* bg  = (const float*)d_in[2];
    const float* Wih = (const float*)d_in[3];
    const float* Whh = (const float*)d_in[4];
    const float* bih = (const float*)d_in[5];
    const float* bhh = (const float*)d_in[6];
    float* out = (float*)d_out;

    const int clearN = MASK_WORDS / 4;                  // uint4 stores
    const int hopN   = T_SNAP * EQ * W_WORDS;           // (t, e, w) threads

    k_clear<<<(clearN + 255) / 256, 256>>>();
    k_seed <<<(EQ + 255) / 256, 256>>>(ei);
    k_copy <<<(clearN + 255) / 256, 256>>>(0);          // B = A (seeds)
    k_hop  <<<(hopN + 255) / 256, 256>>>(ei);           // hop 1 -> B
    k_copy <<<(clearN + 255) / 256, 256>>>(1);          // A = B (hop1 result)
    k_hop  <<<(hopN + 255) / 256, 256>>>(ei);           // hop 2 -> B (final)
    k_incl <<<(hopN + 255) / 256, 256>>>(ei);
    k_top3 <<<(T_SNAP * EQ + 255) / 256, 256>>>();
    k_gru  <<<(EQ * 3) / 128, 128>>>(Wg, bg, Wih, Whh, bih, bhh, out);
}

// round 2
// speedup vs baseline: 1.4313x; 1.4313x over previous
#include <cuda_runtime.h>
#include <math.h>

#define T_SNAP 4
#define EQ     4096
#define NNODES 8192
#define H      32
#define W_WORDS 128              // EQ/32 bit-words per node mask
#define V_VEC  32                // uint4 chunks per node mask (128/4)
#define CAP    512               // per-(t,q) included-edge list capacity
#define HT     16384             // hash table slots (power of 2)
#define NB     (EQ * 3)          // pooled nodes (GRU batch)

#define MASK_WORDS (T_SNAP * 2 * NNODES * W_WORDS)  // 8,388,608 words = 32MB

// Scratch (static device globals — no runtime allocation)
__device__ __align__(16) unsigned g_RA[MASK_WORDS];
__device__ __align__(16) unsigned g_RB[MASK_WORDS];
__device__ int    g_cnt[T_SNAP * EQ];
__device__ int    g_list[T_SNAP * EQ * CAP];
__device__ float  g_tops[T_SNAP * EQ * 3];
__device__ float  g_gi[256 * 3 * H];       // gi(v) table: 256 degrees x 96
__device__ int    g_htkey[HT];
__device__ float4 g_slotv[HT];
__device__ float  g_uh[HT * H];
__device__ int    g_bslot[NB];
__device__ int    g_uniq[NB];
__device__ int    g_uniq_cnt;

__device__ __forceinline__ int moff4(int t, int m, int n, int v) {
    return ((t * 2 + m) * NNODES + n) * V_VEC + v;   // uint4 index
}

// ---------------------------------------------------------------------------
// 1) clear both mask buffers + counters + hash table
__global__ void k_clear() {
    int i = blockIdx.x * blockDim.x + threadIdx.x;
    const uint4 z = make_uint4(0u, 0u, 0u, 0u);
    if (i < MASK_WORDS / 4)            ((uint4*)g_RA)[i] = z;
    else if (i < MASK_WORDS / 2)       ((uint4*)g_RB)[i - MASK_WORDS / 4] = z;
    if (i < T_SNAP * EQ) g_cnt[i] = 0;
    if (i < HT)          g_htkey[i] = -1;
    if (i == 0)          g_uniq_cnt = 0;
}

// 2) seed both A and B: bit q at node uq[q] (mask 0) / vq[q] (mask 1), all t
__global__ void k_seed(const int* __restrict__ ei) {
    int q = blockIdx.x * blockDim.x + threadIdx.x;
    if (q >= EQ) return;
    int u = ei[(T_SNAP - 1) * 2 * EQ + q];
    int v = ei[(T_SNAP - 1) * 2 * EQ + EQ + q];
    unsigned bit = 1u << (q & 31);
    int w = q >> 5;
#pragma unroll
    for (int t = 0; t < T_SNAP; t++) {
        int o0u = ((t * 2 + 0) * NNODES + u) * W_WORDS + w;
        int o1v = ((t * 2 + 1) * NNODES + v) * W_WORDS + w;
        atomicOr(&g_RA[o0u], bit);
        atomicOr(&g_RA[o1v], bit);
        atomicOr(&g_RB[o0u], bit);
        atomicOr(&g_RB[o1v], bit);
    }
}

// 3) copy B -> A (A = R1 before hop 2)
__global__ void k_copy() {
    int i = blockIdx.x * blockDim.x + threadIdx.x;
    if (i < MASK_WORDS / 4) ((uint4*)g_RA)[i] = ((const uint4*)g_RB)[i];
}

// 4) one backward hop (simultaneous semantics), uint4-vectorized.
//    dir=0: read A, OR into B (hop1; B pre-seeded = A).
//    dir=1: read B, OR into A (hop2; A = copy of R1).
__global__ void k_hop(const int* __restrict__ ei, int dir) {
    int idx = blockIdx.x * blockDim.x + threadIdx.x;
    if (idx >= T_SNAP * EQ * V_VEC) return;
    int v = idx & (V_VEC - 1);
    int e = (idx >> 5) & (EQ - 1);
    int t = idx >> 17;
    int src = __ldg(&ei[t * 2 * EQ + e]);
    int dst = __ldg(&ei[t * 2 * EQ + EQ + e]);
    const uint4* R = dir ? (const uint4*)g_RB : (const uint4*)g_RA;
    unsigned*    Wb = dir ? g_RA : g_RB;

#pragma unroll
    for (int m = 0; m < 2; m++) {
        uint4 a = R[moff4(t, m, dst, v)];
        if (a.x | a.y | a.z | a.w) {
            unsigned* p = &Wb[moff4(t, m, src, v) * 4];
            if (a.x) atomicOr(p + 0, a.x);
            if (a.y) atomicOr(p + 1, a.y);
            if (a.z) atomicOr(p + 2, a.z);
            if (a.w) atomicOr(p + 3, a.w);
        }
    }
}

// 5) inclusion: edge in q's merged subgraph iff both endpoints reached from u,
//    or both from v. Final masks R2 live in A. Append dst to q's list.
__global__ void k_incl(const int* __restrict__ ei) {
    int idx = blockIdx.x * blockDim.x + threadIdx.x;
    if (idx >= T_SNAP * EQ * V_VEC) return;
    int v = idx & (V_VEC - 1);
    int e = (idx >> 5) & (EQ - 1);
    int t = idx >> 17;
    int src = __ldg(&ei[t * 2 * EQ + e]);
    int dst = __ldg(&ei[t * 2 * EQ + EQ + e]);
    const uint4* R = (const uint4*)g_RA;
    uint4 s0 = R[moff4(t, 0, src, v)];
    uint4 d0 = R[moff4(t, 0, dst, v)];
    uint4 s1 = R[moff4(t, 1, src, v)];
    uint4 d1 = R[moff4(t, 1, dst, v)];
    unsigned mw[4];
    mw[0] = (s0.x & d0.x) | (s1.x & d1.x);
    mw[1] = (s0.y & d0.y) | (s1.y & d1.y);
    mw[2] = (s0.z & d0.z) | (s1.z & d1.z);
    mw[3] = (s0.w & d0.w) | (s1.w & d1.w);
#pragma unroll
    for (int c = 0; c < 4; c++) {
        unsigned m = mw[c];
        int qbase = ((v * 4 + c) << 5);
        while (m) {
            int b = __ffs(m) - 1;
            m &= m - 1;
            int q = qbase + b;
            int pos = atomicAdd(&g_cnt[t * EQ + q], 1);
            if (pos < CAP) g_list[(t * EQ + q) * CAP + pos] = dst;
        }
    }
}

// 6) top-3 in-degree values per (t, q)
__global__ void k_top3() {
    int idx = blockIdx.x * blockDim.x + threadIdx.x;
    if (idx >= T_SNAP * EQ) return;
    int k = g_cnt[idx];
    if (k > CAP) k = CAP;
    const int* lst = &g_list[idx * CAP];
    float t0 = 0.f, t1 = 0.f, t2 = 0.f;
    for (int i = 0; i < k; i++) {
        int d = lst[i];
        bool dup = false;
        for (int j = 0; j < i; j++)
            if (lst[j] == d) { dup = true; break; }
        if (dup) continue;
        int c = 1;
        for (int j = i + 1; j < k; j++)
            if (lst[j] == d) c++;
        float f = (float)c;
        if (f > t0)      { t2 = t1; t1 = t0; t0 = f; }
        else if (f > t1) { t2 = t1; t1 = f; }
        else if (f > t2) { t2 = f; }
    }
    g_tops[idx * 3 + 0] = t0;
    g_tops[idx * 3 + 1] = t1;
    g_tops[idx * 3 + 2] = t2;
}

// 7) gi(v) table: gi[j] = bih[j] + sum_k Wih[j,k] * relu(v*Wg[k] + bg[k])
__global__ void k_gitab(const float* __restrict__ Wg,  const float* __restrict__ bg,
                        const float* __restrict__ Wih, const float* __restrict__ bih) {
    int idx = blockIdx.x * blockDim.x + threadIdx.x;
    if (idx >= 256 * 3 * H) return;
    int v = idx / (3 * H);
    int j = idx - v * (3 * H);
    float acc = bih[j];
    float fv = (float)v;
#pragma unroll
    for (int kk = 0; kk < H; kk++) {
        float xk = fmaxf(fv * Wg[kk] + bg[kk], 0.f);
        acc += Wih[j * H + kk] * xk;
    }
    g_gi[idx] = acc;
}

// 8) dedup degree 4-tuples per pooled node via hash table
__global__ void k_key() {
    int b = blockIdx.x * blockDim.x + threadIdx.x;
    if (b >= NB) return;
    int q = b / 3, p = b - q * 3;
    float v0 = g_tops[(0 * EQ + q) * 3 + p];
    float v1 = g_tops[(1 * EQ + q) * 3 + p];
    float v2 = g_tops[(2 * EQ + q) * 3 + p];
    float v3 = g_tops[(3 * EQ + q) * 3 + p];
    int i0 = (int)v0, i1 = (int)v1, i2 = (int)v2, i3 = (int)v3;
    int key;
    if (i0 > 254 || i1 > 254 || i2 > 254 || i3 > 254)
        key = (int)(0x80000000u | (unsigned)b);      // unique-self fallback
    else
        key = i0 | (i1 << 8) | (i2 << 16) | (i3 << 24);
    unsigned h = ((unsigned)key * 2654435761u) & (HT - 1);
    int slot = -1;
    for (;;) {
        int old = atomicCAS(&g_htkey[h], -1, key);
        if (old == -1) {
            g_slotv[h] = make_float4(v0, v1, v2, v3);
            int u = atomicAdd(&g_uniq_cnt, 1);
            g_uniq[u] = (int)h;
            slot = (int)h;
            break;
        }
        if (old == key) { slot = (int)h; break; }
        h = (h + 1) & (HT - 1);
    }
    g_bslot[b] = slot;
}

// 9) GRU over unique trajectories: one warp per unique slot, j split over lanes
__global__ void __launch_bounds__(128)
k_gru_u(const float* __restrict__ Wg,  const float* __restrict__ bg,
        const float* __restrict__ Wih, const float* __restrict__ Whh,
        const float* __restrict__ bih, const float* __restrict__ bhh) {
    int cnt = g_uniq_cnt;
    if ((int)blockIdx.x * 4 >= cnt) return;

    __shared__ float sWhhT[H][3 * H];   // [kk][j] transposed, conflict-free
    __shared__ float sbih[3 * H], sbhh[3 * H], sWg[H], sbg[H];
    int tid = threadIdx.x;
    for (int i = tid; i < 3 * H * H; i += 128) {
        int j = i / H, kk = i - j * H;
        sWhhT[kk][j] = Whh[i];
    }
    for (int i = tid; i < 3 * H; i += 128) { sbih[i] = bih[i]; sbhh[i] = bhh[i]; }
    if (tid < H) { sWg[tid] = Wg[tid]; sbg[tid] = bg[tid]; }
    __syncthreads();

    int wg = blockIdx.x * 4 + (tid >> 5);
    if (wg >= cnt) return;
    int lane = tid & 31;
    int slot = g_uniq[wg];
    float4 vv = g_slotv[slot];
    float vs[4] = {vv.x, vv.y, vv.z, vv.w};

    float h = 0.f;
#pragma unroll
    for (int t = 0; t < T_SNAP; t++) {
        float vt = vs[t];
        int iv = (int)vt;
        float gr, gz, gg;
        if (iv >= 0 && iv < 255) {
            const float* gp = &g_gi[iv * 3 * H];
            gr = gp[lane]; gz = gp[H + lane]; gg = gp[2 * H + lane];
        } else {  // rare exact fallback
            gr = sbih[lane]; gz = sbih[H + lane]; gg = sbih[2 * H + lane];
            for (int kk = 0; kk < H; kk++) {
                float xk = fmaxf(vt * sWg[kk] + sbg[kk], 0.f);
                gr += Wih[lane * H + kk] * xk;
                gz += Wih[(H + lane) * H + kk] * xk;
                gg += Wih[(2 * H + lane) * H + kk] * xk;
            }
        }
        float hr = sbhh[lane], hz = sbhh[H + lane], hg = sbhh[2 * H + lane];
#pragma unroll
        for (int kk = 0; kk < H; kk++) {
            float hk = __shfl_sync(0xffffffffu, h, kk);
            hr += sWhhT[kk][lane]         * hk;
            hz += sWhhT[kk][H + lane]     * hk;
            hg += sWhhT[kk][2 * H + lane] * hk;
        }
        float r = 1.f / (1.f + expf(-(gr + hr)));
        float z = 1.f / (1.f + expf(-(gz + hz)));
        float n = tanhf(gg + r * hg);
        h = (1.f - z) * n + z * h;
    }
    g_uh[slot * H + lane] = h;
}

// 10) gather unique results back to all pooled nodes
__global__ void k_gather(float* __restrict__ out) {
    int idx = blockIdx.x * blockDim.x + threadIdx.x;
    if (idx >= NB * H) return;
    int b = idx >> 5;
    int j = idx & (H - 1);
    out[idx] = g_uh[g_bslot[b] * H + j];
}

// ---------------------------------------------------------------------------
extern "C" void kernel_launch(void* const* d_in, const int* in_sizes, int n_in,
                              void* d_out, int out_size) {
    const int*   ei  = (const int*)d_in[0];
    const float* Wg  = (const float*)d_in[1];
    const float* bg  = (const float*)d_in[2];
    const float* Wih = (const float*)d_in[3];
    const float* Whh = (const float*)d_in[4];
    const float* bih = (const float*)d_in[5];
    const float* bhh = (const float*)d_in[6];
    float* out = (float*)d_out;

    const int clearN = MASK_WORDS / 2;        // uint4 slots for A + B
    const int copyN  = MASK_WORDS / 4;
    const int hopN   = T_SNAP * EQ * V_VEC;   // (t, e, vec4) threads

    k_clear<<<(clearN + 255) / 256, 256>>>();
    k_seed <<<(EQ + 255) / 256, 256>>>(ei);
    k_hop  <<<(hopN + 255) / 256, 256>>>(ei, 0);    // hop 1: A -> B
    k_copy <<<(copyN + 255) / 256, 256>>>();        // A = B (R1)
    k_hop  <<<(hopN + 255) / 256, 256>>>(ei, 1);    // hop 2: B -> A (A = R2)
    k_incl <<<(hopN + 255) / 256, 256>>>(ei);
    k_top3 <<<(T_SNAP * EQ + 255) / 256, 256>>>();
    k_gitab<<<(256 * 3 * H + 255) / 256, 256>>>(Wg, bg, Wih, bih);
    k_key  <<<(NB + 255) / 256, 256>>>();
    k_gru_u<<<NB / 4 / 32, 128>>>(Wg, bg, Wih, Whh, bih, bhh);
    k_gather<<<(NB * H + 255) / 256, 256>>>(out);
}

// round 3
// speedup vs baseline: 1.6364x; 1.1434x over previous
#include <cuda_runtime.h>
#include <math.h>

#define T_SNAP 4
#define EQ     4096
#define NNODES 8192
#define H      32
#define BCAP   32                // in-edge bucket capacity per (t, node)
#define RCAP   128               // per-query reach-set capacity
#define HT     16384             // hash table slots (power of 2)
#define NB     (EQ * 3)          // pooled nodes (GRU batch)

// Scratch (static device globals — no runtime allocation)
__device__ int    g_bcnt[T_SNAP * NNODES];
__device__ int    g_bsrc[T_SNAP * NNODES * BCAP];
__device__ float  g_tops[T_SNAP * EQ * 3];
__device__ float  g_gi[256 * 3 * H];       // gi(v) table: 256 degrees x 96
__device__ int    g_htkey[HT];
__device__ float4 g_slotv[HT];
__device__ float  g_uh[HT * H];
__device__ int    g_bslot[NB];
__device__ int    g_uniq[NB];
__device__ int    g_uniq_cnt;

// ---------------------------------------------------------------------------
// 1) clear bucket counters + hash table
__global__ void k_clear() {
    int i = blockIdx.x * blockDim.x + threadIdx.x;
    if (i < T_SNAP * NNODES) g_bcnt[i] = 0;
    if (i < HT)              g_htkey[i] = -1;
    if (i == 0)              g_uniq_cnt = 0;
}

// 2) scatter edges into per-(t, dst) buckets of srcs
__global__ void k_scatter(const int* __restrict__ ei) {
    int idx = blockIdx.x * blockDim.x + threadIdx.x;
    if (idx >= T_SNAP * EQ) return;
    int t = idx >> 12;                 // EQ = 4096
    int e = idx & (EQ - 1);
    int src = ei[t * 2 * EQ + e];
    int dst = ei[t * 2 * EQ + EQ + e];
    int pos = atomicAdd(&g_bcnt[t * NNODES + dst], 1);
    if (pos < BCAP) g_bsrc[(t * NNODES + dst) * BCAP + pos] = src;
}

// helpers -------------------------------------------------------------------
__device__ __forceinline__ bool in_list(const int* l, int n, int x) {
    for (int i = 0; i < n; i++)
        if (l[i] == x) return true;
    return false;
}

// 2-hop backward BFS from seed within snapshot t; returns set size
__device__ __forceinline__ int bfs2(int t, int seed, int* R) {
    R[0] = seed;
    int n = 1, s = 0, e = 1;
#pragma unroll
    for (int hop = 0; hop < 2; hop++) {
        for (int i = s; i < e; i++) {
            int node = R[i];
            int c = g_bcnt[t * NNODES + node];
            if (c > BCAP) c = BCAP;
            const int* b = &g_bsrc[(t * NNODES + node) * BCAP];
            for (int j = 0; j < c; j++) {
                int src = b[j];
                if (!in_list(R, n, src) && n < RCAP) R[n++] = src;
            }
        }
        s = e; e = n;
    }
    return n;
}

// 3) per-(t, q): reach sets, merged-subgraph in-degrees, top-3
__global__ void k_query(const int* __restrict__ ei) {
    int idx = blockIdx.x * blockDim.x + threadIdx.x;
    if (idx >= T_SNAP * EQ) return;
    int t = idx >> 12;
    int q = idx & (EQ - 1);
    int u = ei[(T_SNAP - 1) * 2 * EQ + q];
    int v = ei[(T_SNAP - 1) * 2 * EQ + EQ + q];

    int Ru[RCAP], Rv[RCAP];
    int nu = bfs2(t, u, Ru);
    int nv = bfs2(t, v, Rv);

    float t0 = 0.f, t1 = 0.f, t2 = 0.f;

    // iterate union of Ru, Rv; for each node count included in-edges
    for (int pass = 0; pass < 2; pass++) {
        const int* L = pass ? Rv : Ru;
        int nL = pass ? nv : nu;
        for (int i = 0; i < nL; i++) {
            int node = L[i];
            bool inRu, inRv;
            if (pass == 0) {
                inRu = true;
                inRv = in_list(Rv, nv, node);
            } else {
                inRu = in_list(Ru, nu, node);
                if (inRu) continue;        // already handled in pass 0
                inRv = true;
            }
            int c = g_bcnt[t * NNODES + node];
            if (c > BCAP) c = BCAP;
            const int* b = &g_bsrc[(t * NNODES + node) * BCAP];
            int d = 0;
            for (int j = 0; j < c; j++) {
                int src = b[j];
                bool su = inRu && in_list(Ru, nu, src);
                bool sv = inRv && in_list(Rv, nv, src);
                if (su || sv) d++;
            }
            float f = (float)d;
            if (f > t0)      { t2 = t1; t1 = t0; t0 = f; }
            else if (f > t1) { t2 = t1; t1 = f; }
            else if (f > t2) { t2 = f; }
        }
    }
    g_tops[idx * 3 + 0] = t0;
    g_tops[idx * 3 + 1] = t1;
    g_tops[idx * 3 + 2] = t2;
}

// 4) gi(v) table: gi[j] = bih[j] + sum_k Wih[j,k] * relu(v*Wg[k] + bg[k])
__global__ void k_gitab(const float* __restrict__ Wg,  const float* __restrict__ bg,
                        const float* __restrict__ Wih, const float* __restrict__ bih) {
    int idx = blockIdx.x * blockDim.x + threadIdx.x;
    if (idx >= 256 * 3 * H) return;
    int v = idx / (3 * H);
    int j = idx - v * (3 * H);
    float acc = bih[j];
    float fv = (float)v;
#pragma unroll
    for (int kk = 0; kk < H; kk++) {
        float xk = fmaxf(fv * Wg[kk] + bg[kk], 0.f);
        acc += Wih[j * H + kk] * xk;
    }
    g_gi[idx] = acc;
}

// 5) dedup degree 4-tuples per pooled node via hash table
__global__ void k_key() {
    int b = blockIdx.x * blockDim.x + threadIdx.x;
    if (b >= NB) return;
    int q = b / 3, p = b - q * 3;
    float v0 = g_tops[(0 * EQ + q) * 3 + p];
    float v1 = g_tops[(1 * EQ + q) * 3 + p];
    float v2 = g_tops[(2 * EQ + q) * 3 + p];
    float v3 = g_tops[(3 * EQ + q) * 3 + p];
    int i0 = (int)v0, i1 = (int)v1, i2 = (int)v2, i3 = (int)v3;
    int key;
    if (i0 > 254 || i1 > 254 || i2 > 254 || i3 > 254)
        key = (int)(0x80000000u | (unsigned)b);      // unique-self fallback
    else
        key = i0 | (i1 << 8) | (i2 << 16) | (i3 << 24);
    unsigned h = ((unsigned)key * 2654435761u) & (HT - 1);
    int slot = -1;
    for (;;) {
        int old = atomicCAS(&g_htkey[h], -1, key);
        if (old == -1) {
            g_slotv[h] = make_float4(v0, v1, v2, v3);
            int u = atomicAdd(&g_uniq_cnt, 1);
            g_uniq[u] = (int)h;
            slot = (int)h;
            break;
        }
        if (old == key) { slot = (int)h; break; }
        h = (h + 1) & (HT - 1);
    }
    g_bslot[b] = slot;
}

// 6) GRU over unique trajectories: one warp per unique slot, j split over lanes
__global__ void __launch_bounds__(128)
k_gru_u(const float* __restrict__ Wg,  const float* __restrict__ bg,
        const float* __restrict__ Wih, const float* __restrict__ Whh,
        const float* __restrict__ bih, const float* __restrict__ bhh) {
    int cnt = g_uniq_cnt;
    if ((int)blockIdx.x * 4 >= cnt) return;

    __shared__ float sWhhT[H][3 * H];   // [kk][j] transposed, conflict-free
    __shared__ float sbih[3 * H], sbhh[3 * H], sWg[H], sbg[H];
    int tid = threadIdx.x;
    for (int i = tid; i < 3 * H * H; i += 128) {
        int j = i / H, kk = i - j * H;
        sWhhT[kk][j] = Whh[i];
    }
    for (int i = tid; i < 3 * H; i += 128) { sbih[i] = bih[i]; sbhh[i] = bhh[i]; }
    if (tid < H) { sWg[tid] = Wg[tid]; sbg[tid] = bg[tid]; }
    __syncthreads();

    int wg = blockIdx.x * 4 + (tid >> 5);
    if (wg >= cnt) return;
    int lane = tid & 31;
    int slot = g_uniq[wg];
    float4 vv = g_slotv[slot];
    float vs[4] = {vv.x, vv.y, vv.z, vv.w};

    float h = 0.f;
#pragma unroll
    for (int t = 0; t < T_SNAP; t++) {
        float vt = vs[t];
        int iv = (int)vt;
        float gr, gz, gg;
        if (iv >= 0 && iv < 255) {
            const float* gp = &g_gi[iv * 3 * H];
            gr = gp[lane]; gz = gp[H + lane]; gg = gp[2 * H + lane];
        } else {  // rare exact fallback
            gr = sbih[lane]; gz = sbih[H + lane]; gg = sbih[2 * H + lane];
            for (int kk = 0; kk < H; kk++) {
                float xk = fmaxf(vt * sWg[kk] + sbg[kk], 0.f);
                gr += Wih[lane * H + kk] * xk;
                gz += Wih[(H + lane) * H + kk] * xk;
                gg += Wih[(2 * H + lane) * H + kk] * xk;
            }
        }
        float hr = sbhh[lane], hz = sbhh[H + lane], hg = sbhh[2 * H + lane];
#pragma unroll
        for (int kk = 0; kk < H; kk++) {
            float hk = __shfl_sync(0xffffffffu, h, kk);
            hr += sWhhT[kk][lane]         * hk;
            hz += sWhhT[kk][H + lane]     * hk;
            hg += sWhhT[kk][2 * H + lane] * hk;
        }
        float r = 1.f / (1.f + expf(-(gr + hr)));
        float z = 1.f / (1.f + expf(-(gz + hz)));
        float n = tanhf(gg + r * hg);
        h = (1.f - z) * n + z * h;
    }
    g_uh[slot * H + lane] = h;
}

// 7) gather unique results back to all pooled nodes
__global__ void k_gather(float* __restrict__ out) {
    int idx = blockIdx.x * blockDim.x + threadIdx.x;
    if (idx >= NB * H) return;
    int b = idx >> 5;
    int j = idx & (H - 1);
    out[idx] = g_uh[g_bslot[b] * H + j];
}

// ---------------------------------------------------------------------------
extern "C" void kernel_launch(void* const* d_in, const int* in_sizes, int n_in,
                              void* d_out, int out_size) {
    const int*   ei  = (const int*)d_in[0];
    const float* Wg  = (const float*)d_in[1];
    const float* bg  = (const float*)d_in[2];
    const float* Wih = (const float*)d_in[3];
    const float* Whh = (const float*)d_in[4];
    const float* bih = (const float*)d_in[5];
    const float* bhh = (const float*)d_in[6];
    float* out = (float*)d_out;

    k_clear  <<<(T_SNAP * NNODES + 255) / 256, 256>>>();
    k_scatter<<<(T_SNAP * EQ + 255) / 256, 256>>>(ei);
    k_query  <<<(T_SNAP * EQ + 255) / 256, 256>>>(ei);
    k_gitab  <<<(256 * 3 * H + 255) / 256, 256>>>(Wg, bg, Wih, bih);
    k_key    <<<(NB + 255) / 256, 256>>>();
    k_gru_u  <<<NB / 4 / 32, 128>>>(Wg, bg, Wih, Whh, bih, bhh);
    k_gather <<<(NB * H + 255) / 256, 256>>>(out);
}